// round 1
// baseline (speedup 1.0000x reference)
#include <cuda_runtime.h>
#include <cstdint>

#define NODES   16384
#define NPG     128      // nodes per graph
#define NG      128      // graphs
#define HID     128
#define KNN     24

// ---------------- scratch (device globals; no allocation) ----------------
__device__ float g_feat_a[NODES * HID];
__device__ float g_feat_b[NODES * HID];
__device__ float g_pq[NODES * 2 * HID];     // per node: [p(128) | q(128)]
__device__ float g_wc[HID * 2 * HID];       // [Wa-Wb | Wb] as 128 x 256

__device__ __forceinline__ float elu_fast(float v) {
    return v > 0.0f ? v : (__expf(v) - 1.0f);
}

// ---------------- generic tiled fp32 matmul: C = act(A*B + bias) ----------
// A: MxK row-major, B: KxN row-major, C: MxN row-major.
// M%64==0, N%64==0, K%16==0 guaranteed by caller.
__global__ __launch_bounds__(256) void mm_kernel(
    const float* __restrict__ A, const float* __restrict__ B,
    const float* __restrict__ bias, int biasLimit, int doElu,
    float* __restrict__ C, int M, int N, int K)
{
    __shared__ float As[16][68];   // [k][m], pad 4 for bank/alignment
    __shared__ float Bs[16][64];   // [k][n]

    const int tid = threadIdx.x;
    const int tx = tid & 15;       // 0..15  -> 4 cols each
    const int ty = tid >> 4;       // 0..15  -> 4 rows each
    const int rowBase = blockIdx.x * 64;
    const int colBase = blockIdx.y * 64;

    float acc[4][4];
#pragma unroll
    for (int r = 0; r < 4; r++)
#pragma unroll
        for (int c = 0; c < 4; c++) acc[r][c] = 0.0f;

    for (int kk = 0; kk < K; kk += 16) {
#pragma unroll
        for (int t = 0; t < 4; t++) {
            int idx = t * 256 + tid;
            int m = idx >> 4, k = idx & 15;
            As[k][m] = A[(rowBase + m) * K + kk + k];
        }
#pragma unroll
        for (int t = 0; t < 4; t++) {
            int idx = t * 256 + tid;
            int k = idx >> 6, n = idx & 63;
            Bs[k][n] = B[(kk + k) * N + colBase + n];
        }
        __syncthreads();
#pragma unroll
        for (int k = 0; k < 16; k++) {
            float4 a = *(const float4*)&As[k][ty * 4];
            float4 b = *(const float4*)&Bs[k][tx * 4];
            float av[4] = {a.x, a.y, a.z, a.w};
            float bv[4] = {b.x, b.y, b.z, b.w};
#pragma unroll
            for (int r = 0; r < 4; r++)
#pragma unroll
                for (int c = 0; c < 4; c++) acc[r][c] += av[r] * bv[c];
        }
        __syncthreads();
    }

#pragma unroll
    for (int r = 0; r < 4; r++) {
        int row = rowBase + ty * 4 + r;
#pragma unroll
        for (int c = 0; c < 4; c++) {
            int col = colBase + tx * 4 + c;
            float v = acc[r][c];
            if (col < biasLimit) v += bias[col];
            if (doElu) v = elu_fast(v);
            C[row * N + col] = v;
        }
    }
}

// ---------------- build [Wa-Wb | Wb] (128 x 256) from conv_w (256 x 128) ---
__global__ void build_wcat(const float* __restrict__ w, float* __restrict__ wc)
{
    int idx = blockIdx.x * 256 + threadIdx.x;   // 0..32767
    int d = idx >> 8;        // 0..127
    int n = idx & 255;       // 0..255
    float v;
    if (n < 128) v = w[d * 128 + n] - w[(128 + d) * 128 + n];
    else         v = w[(128 + d) * 128 + (n - 128)];
    wc[idx] = v;
}

// ---------------- fused per-graph kNN + top-k + edge aggregate -------------
// One block per graph (128 blocks, 256 threads).
// smem: sXT [128][132] (X transposed, feat-major), sD [128][129] (d2),
//       sQ [128][128], sSq[128]
#define SXT_STRIDE 132
#define SD_STRIDE  129
#define SMEM_KNN ((128*SXT_STRIDE + 128*SD_STRIDE + 128*128 + 128) * 4)

__global__ __launch_bounds__(256, 1) void knn_agg(
    const float* __restrict__ X, const float* __restrict__ PQ,
    float* __restrict__ OUT)
{
    extern __shared__ float sm[];
    float* sXT = sm;                              // [d][n]
    float* sD  = sXT + 128 * SXT_STRIDE;          // [i][j]
    float* sQ  = sD + 128 * SD_STRIDE;            // [n][f]
    float* sSq = sQ + 128 * 128;                  // [n]

    const int g   = blockIdx.x;
    const int tid = threadIdx.x;
    const float* Xg  = X  + (size_t)g * NPG * HID;
    const float* PQg = PQ + (size_t)g * NPG * 2 * HID;

    // load X (transposed) and q tile
    for (int idx = tid; idx < NPG * HID; idx += 256) {
        int n = idx >> 7, f = idx & 127;
        float xv = Xg[idx];
        sXT[f * SXT_STRIDE + n] = xv;
        sQ[n * 128 + f] = PQg[n * 256 + 128 + f];
    }
    __syncthreads();

    if (tid < 128) {
        float s = 0.0f;
        for (int d = 0; d < 128; d++) {
            float v = sXT[d * SXT_STRIDE + tid];
            s += v * v;
        }
        sSq[tid] = s;
    }
    __syncthreads();

    // Gram matrix: 16x16 threads, each an 8x8 tile of the 128x128 output
    {
        const int tx = tid & 15, ty = tid >> 4;
        const int i0 = ty * 8, j0 = tx * 8;
        float acc[8][8];
#pragma unroll
        for (int r = 0; r < 8; r++)
#pragma unroll
            for (int c = 0; c < 8; c++) acc[r][c] = 0.0f;

#pragma unroll 2
        for (int d = 0; d < 128; d++) {
            const float* rowp = sXT + d * SXT_STRIDE;
            float4 a0 = *(const float4*)(rowp + i0);
            float4 a1 = *(const float4*)(rowp + i0 + 4);
            float4 b0 = *(const float4*)(rowp + j0);
            float4 b1 = *(const float4*)(rowp + j0 + 4);
            float av[8] = {a0.x,a0.y,a0.z,a0.w,a1.x,a1.y,a1.z,a1.w};
            float bv[8] = {b0.x,b0.y,b0.z,b0.w,b1.x,b1.y,b1.z,b1.w};
#pragma unroll
            for (int r = 0; r < 8; r++)
#pragma unroll
                for (int c = 0; c < 8; c++) acc[r][c] += av[r] * bv[c];
        }
#pragma unroll
        for (int r = 0; r < 8; r++) {
            int i = i0 + r;
            float sqi = sSq[i];
#pragma unroll
            for (int c = 0; c < 8; c++) {
                int j = j0 + c;
                sD[i * SD_STRIDE + j] = sqi + sSq[j] - 2.0f * acc[r][c];
            }
        }
    }
    __syncthreads();

    // per-row top-24 (smallest d2, tie -> lowest index, matching top_k) + aggregate
    const int w = tid >> 5;     // warp 0..7
    const int l = tid & 31;     // lane
    for (int rr = 0; rr < 16; rr++) {
        int i = w * 16 + rr;
        float d2v[4], pi[4], accv[4];
#pragma unroll
        for (int c = 0; c < 4; c++) {
            int j = l + 32 * c;
            d2v[c] = sD[i * SD_STRIDE + j];
            pi[c]  = PQg[i * 256 + l + 32 * c];
            accv[c] = -3.0e38f;
        }
#pragma unroll 1
        for (int it = 0; it < KNN; it++) {
            // local min (ascending j order preserves lowest-index tie-break)
            float bv = d2v[0]; int bj = l;
#pragma unroll
            for (int c = 1; c < 4; c++) {
                int jj = l + 32 * c;
                if (d2v[c] < bv) { bv = d2v[c]; bj = jj; }
            }
            // warp argmin
#pragma unroll
            for (int off = 16; off > 0; off >>= 1) {
                float ov = __shfl_down_sync(0xffffffffu, bv, off);
                int   oj = __shfl_down_sync(0xffffffffu, bj, off);
                if (ov < bv || (ov == bv && oj < bj)) { bv = ov; bj = oj; }
            }
            bj = __shfl_sync(0xffffffffu, bj, 0);
            if ((bj & 31) == l) d2v[bj >> 5] = 3.4e38f;

            const float* qrow = sQ + bj * 128;
#pragma unroll
            for (int c = 0; c < 4; c++) {
                float v = pi[c] + qrow[l + 32 * c];
                float h = elu_fast(v);
                accv[c] = fmaxf(accv[c], h);
            }
        }
        float* orow = OUT + ((size_t)g * NPG + i) * HID;
#pragma unroll
        for (int c = 0; c < 4; c++) orow[l + 32 * c] = accv[c];
    }
}

// ---------------- sum-pool + output MLP (one block per graph) --------------
__global__ __launch_bounds__(128) void pool_mlp(
    const float* __restrict__ X,
    const float* __restrict__ w1, const float* __restrict__ b1,
    const float* __restrict__ w2, const float* __restrict__ b2,
    const float* __restrict__ w3, const float* __restrict__ b3,
    const float* __restrict__ w4, const float* __restrict__ b4,
    float* __restrict__ out)
{
    __shared__ float pooled[128];
    __shared__ float o1[64];
    __shared__ float o2[32];
    __shared__ float o3[32];
    const int g = blockIdx.x, t = threadIdx.x;
    const float* Xg = X + (size_t)g * NPG * HID;

    float s = 0.0f;
    for (int n = 0; n < NPG; n++) s += Xg[n * HID + t];
    pooled[t] = s;
    __syncthreads();

    if (t < 64) {
        float a = b1[t];
        for (int d = 0; d < 128; d++) a += pooled[d] * w1[d * 64 + t];
        o1[t] = elu_fast(a);
    }
    __syncthreads();
    if (t < 32) {
        float a = b2[t];
        for (int d = 0; d < 64; d++) a += o1[d] * w2[d * 32 + t];
        o2[t] = elu_fast(a);
    }
    __syncthreads();
    if (t < 32) {
        float a = b3[t];
        for (int d = 0; d < 32; d++) a += o2[d] * w3[d * 32 + t];
        o3[t] = elu_fast(a);
    }
    __syncthreads();
    if (t < 6) {
        float a = b4[t];
        for (int d = 0; d < 32; d++) a += o3[d] * w4[d * 6 + t];
        out[g * 6 + t] = a;
    }
}

// ---------------- batch passthrough (int32 -> float) -----------------------
__global__ void copy_batch(const int* __restrict__ b, float* __restrict__ out)
{
    int i = blockIdx.x * 256 + threadIdx.x;
    if (i < NODES) out[i] = (float)b[i];
}

// ---------------------------------------------------------------------------
extern "C" void kernel_launch(void* const* d_in, const int* in_sizes, int n_in,
                              void* d_out, int out_size)
{
    const float* x_pf    = (const float*)d_in[0];
    const float* enc_w1  = (const float*)d_in[1];
    const float* enc_b1  = (const float*)d_in[2];
    const float* enc_w2  = (const float*)d_in[3];
    const float* enc_b2  = (const float*)d_in[4];
    const float* conv_w[3] = {(const float*)d_in[5], (const float*)d_in[7], (const float*)d_in[9]};
    const float* conv_b[3] = {(const float*)d_in[6], (const float*)d_in[8], (const float*)d_in[10]};
    const float* out_w1  = (const float*)d_in[11];
    const float* out_b1  = (const float*)d_in[12];
    const float* out_w2  = (const float*)d_in[13];
    const float* out_b2  = (const float*)d_in[14];
    const float* out_w3  = (const float*)d_in[15];
    const float* out_b3  = (const float*)d_in[16];
    const float* out_w4  = (const float*)d_in[17];
    const float* out_b4  = (const float*)d_in[18];
    const int*   batch   = (const int*)d_in[19];

    float *featA, *featB, *pq, *wc;
    cudaGetSymbolAddress((void**)&featA, g_feat_a);
    cudaGetSymbolAddress((void**)&featB, g_feat_b);
    cudaGetSymbolAddress((void**)&pq,    g_pq);
    cudaGetSymbolAddress((void**)&wc,    g_wc);

    cudaFuncSetAttribute(knn_agg, cudaFuncAttributeMaxDynamicSharedMemorySize, SMEM_KNN);

    // encoder
    mm_kernel<<<dim3(NODES / 64, 2), 256>>>(x_pf,  enc_w1, enc_b1, 128, 1, featB, NODES, 128, 16);
    mm_kernel<<<dim3(NODES / 64, 2), 256>>>(featB, enc_w2, enc_b2, 128, 1, featA, NODES, 128, 128);

    // 3 dynamic edge convs
    float* cur = featA;
    float* nxt = featB;
    for (int cidx = 0; cidx < 3; cidx++) {
        build_wcat<<<128, 256>>>(conv_w[cidx], wc);
        mm_kernel<<<dim3(NODES / 64, 4), 256>>>(cur, wc, conv_b[cidx], 128, 0, pq, NODES, 256, 128);
        knn_agg<<<NG, 256, SMEM_KNN>>>(cur, pq, nxt);
        float* t = cur; cur = nxt; nxt = t;
    }

    // pool + output MLP
    pool_mlp<<<NG, 128>>>(cur, out_w1, out_b1, out_w2, out_b2,
                          out_w3, out_b3, out_w4, out_b4, (float*)d_out);

    // batch_pf passthrough after the 128*6 outputs
    copy_batch<<<(NODES + 255) / 256, 256>>>(batch, (float*)d_out + NG * 6);
}

// round 2
// speedup vs baseline: 1.5867x; 1.5867x over previous
#include <cuda_runtime.h>
#include <cstdint>

#define NODES   16384
#define NPG     128
#define NG      128
#define HID     128
#define KNN     24

// ---------------- scratch ----------------
__device__ float g_feat_a[NODES * HID];
__device__ float g_feat_b[NODES * HID];
__device__ float g_pq[NODES * 2 * HID];
__device__ float g_wc[HID * 2 * HID];

__device__ __forceinline__ float elu_fast(float v) {
    return v > 0.0f ? v : (__expf(v) - 1.0f);
}

// monotone float->uint key map (total order == float <)
__device__ __forceinline__ unsigned fkey(float v) {
    unsigned b = __float_as_uint(v);
    return b ^ ((b & 0x80000000u) ? 0xffffffffu : 0x80000000u);
}

// ---------------- 128x128-tile fp32 matmul: C = act(A*B + bias) ------------
// A: MxK row-major, B: KxN row-major, C: MxN. M%128==0, N%128==0, K%16==0.
__global__ __launch_bounds__(256) void mm_kernel(
    const float* __restrict__ A, const float* __restrict__ B,
    const float* __restrict__ bias, int biasLimit, int doElu,
    float* __restrict__ C, int M, int N, int K)
{
    __shared__ float As[16 * 132];   // [k][m], stride 132
    __shared__ float Bs[16 * 128];   // [k][n]

    const int tid = threadIdx.x;
    const int tx = tid & 15;         // n-tile 0..15
    const int ty = tid >> 4;         // m-tile 0..15
    const int rowBase = blockIdx.x * 128;
    const int colBase = blockIdx.y * 128;

    float acc[8][8];
#pragma unroll
    for (int r = 0; r < 8; r++)
#pragma unroll
        for (int c = 0; c < 8; c++) acc[r][c] = 0.0f;

    for (int kk = 0; kk < K; kk += 16) {
#pragma unroll
        for (int t = 0; t < 8; t++) {
            int idx = t * 256 + tid;
            int m = idx >> 4, k = idx & 15;
            As[k * 132 + m] = A[(size_t)(rowBase + m) * K + kk + k];
        }
#pragma unroll
        for (int t = 0; t < 8; t++) {
            int idx = t * 256 + tid;
            int k = idx >> 7, n = idx & 127;
            Bs[k * 128 + n] = B[(size_t)(kk + k) * N + colBase + n];
        }
        __syncthreads();
#pragma unroll
        for (int k = 0; k < 16; k++) {
            float4 a0 = *(const float4*)&As[k * 132 + ty * 8];
            float4 a1 = *(const float4*)&As[k * 132 + ty * 8 + 4];
            float4 b0 = *(const float4*)&Bs[k * 128 + tx * 8];
            float4 b1 = *(const float4*)&Bs[k * 128 + tx * 8 + 4];
            float av[8] = {a0.x,a0.y,a0.z,a0.w,a1.x,a1.y,a1.z,a1.w};
            float bv[8] = {b0.x,b0.y,b0.z,b0.w,b1.x,b1.y,b1.z,b1.w};
#pragma unroll
            for (int r = 0; r < 8; r++)
#pragma unroll
                for (int c = 0; c < 8; c++) acc[r][c] += av[r] * bv[c];
        }
        __syncthreads();
    }

#pragma unroll
    for (int r = 0; r < 8; r++) {
        int row = rowBase + ty * 8 + r;
#pragma unroll
        for (int c = 0; c < 8; c++) {
            int col = colBase + tx * 8 + c;
            float v = acc[r][c];
            if (col < biasLimit) v += bias[col];
            if (doElu) v = elu_fast(v);
            C[(size_t)row * N + col] = v;
        }
    }
}

// ---------------- build [Wa-Wb | Wb] (128 x 256) from conv_w (256 x 128) ---
__global__ void build_wcat(const float* __restrict__ w, float* __restrict__ wc)
{
    int idx = blockIdx.x * 256 + threadIdx.x;   // 0..32767
    int d = idx >> 8;
    int n = idx & 255;
    float v;
    if (n < 128) v = w[d * 128 + n] - w[(128 + d) * 128 + n];
    else         v = w[(128 + d) * 128 + (n - 128)];
    wc[idx] = v;
}

// ---------------- fused per-graph kNN + radix top-k + aggregate ------------
#define SXT_S 132
#define SD_S  132
// floats: sXT 128*132 + sD 128*132 + sQ 128*128 + sSq 128 + sList 128*24(int)
#define SMEM_KNN ((128*SXT_S + 128*SD_S + 128*128 + 128 + 128*KNN) * 4)

__global__ __launch_bounds__(512, 1) void knn_agg(
    const float* __restrict__ X, const float* __restrict__ PQ,
    float* __restrict__ OUT)
{
    extern __shared__ float sm[];
    float* sXT = sm;                         // [f][n] stride 132
    float* sD  = sXT + 128 * SXT_S;          // [i][j] stride 132
    float* sQ  = sD  + 128 * SD_S;           // [n][f] stride 128
    float* sSq = sQ  + 128 * 128;            // [n]
    int*   sList = (int*)(sSq + 128);        // [i][24]

    const int g   = blockIdx.x;
    const int tid = threadIdx.x;
    const float* Xg  = X  + (size_t)g * NPG * HID;
    const float* PQg = PQ + (size_t)g * NPG * 2 * HID;

    // phase 1: load X (transposed) and q tile
    for (int idx = tid; idx < NPG * HID; idx += 512) {
        int n = idx >> 7, f = idx & 127;
        sXT[f * SXT_S + n] = Xg[idx];
        sQ[n * 128 + f]    = PQg[n * 256 + 128 + f];
    }
    __syncthreads();

    // phase 2: squared norms
    if (tid < 128) {
        float s = 0.0f;
#pragma unroll 4
        for (int d = 0; d < 128; d++) {
            float v = sXT[d * SXT_S + tid];
            s += v * v;
        }
        sSq[tid] = s;
    }
    __syncthreads();

    // phase 3: Gram -> d2 (warps 0-7, 8x8 microtiles)
    if (tid < 256) {
        const int tx = tid & 15, ty = tid >> 4;
        const int i0 = ty * 8, j0 = tx * 8;
        float acc[8][8];
#pragma unroll
        for (int r = 0; r < 8; r++)
#pragma unroll
            for (int c = 0; c < 8; c++) acc[r][c] = 0.0f;

#pragma unroll 2
        for (int d = 0; d < 128; d++) {
            const float* rowp = sXT + d * SXT_S;
            float4 a0 = *(const float4*)(rowp + i0);
            float4 a1 = *(const float4*)(rowp + i0 + 4);
            float4 b0 = *(const float4*)(rowp + j0);
            float4 b1 = *(const float4*)(rowp + j0 + 4);
            float av[8] = {a0.x,a0.y,a0.z,a0.w,a1.x,a1.y,a1.z,a1.w};
            float bv[8] = {b0.x,b0.y,b0.z,b0.w,b1.x,b1.y,b1.z,b1.w};
#pragma unroll
            for (int r = 0; r < 8; r++)
#pragma unroll
                for (int c = 0; c < 8; c++) acc[r][c] += av[r] * bv[c];
        }
#pragma unroll
        for (int r = 0; r < 8; r++) {
            int i = i0 + r;
            float sqi = sSq[i];
            float4 v0, v1;
            v0.x = sqi + sSq[j0+0] - 2.0f*acc[r][0];
            v0.y = sqi + sSq[j0+1] - 2.0f*acc[r][1];
            v0.z = sqi + sSq[j0+2] - 2.0f*acc[r][2];
            v0.w = sqi + sSq[j0+3] - 2.0f*acc[r][3];
            v1.x = sqi + sSq[j0+4] - 2.0f*acc[r][4];
            v1.y = sqi + sSq[j0+5] - 2.0f*acc[r][5];
            v1.z = sqi + sSq[j0+6] - 2.0f*acc[r][6];
            v1.w = sqi + sSq[j0+7] - 2.0f*acc[r][7];
            *(float4*)&sD[i * SD_S + j0]     = v0;
            *(float4*)&sD[i * SD_S + j0 + 4] = v1;
        }
    }
    __syncthreads();

    // phase 4: per-row radix-select threshold + neighbor list + aggregate
    const int w = tid >> 5;          // warp 0..15
    const int l = tid & 31;
    const unsigned lmask = (1u << l) - 1u;
    const int rowBase = w * 8;

    for (int pp = 0; pp < 4; pp++) {
        const int iA = rowBase + 2 * pp;

        unsigned ka[2][4];
#pragma unroll
        for (int rr = 0; rr < 2; rr++)
#pragma unroll
            for (int c = 0; c < 4; c++)
                ka[rr][c] = fkey(sD[(iA + rr) * SD_S + l + 32 * c]);

        // dual binary search for 24th smallest key
        unsigned lo0 = 0, hi0 = 0xffffffffu, lo1 = 0, hi1 = 0xffffffffu;
#pragma unroll 1
        for (int it = 0; it < 32; it++) {
            unsigned m0 = lo0 + ((hi0 - lo0) >> 1);
            unsigned m1 = lo1 + ((hi1 - lo1) >> 1);
            int c0 = (ka[0][0] <= m0) + (ka[0][1] <= m0) + (ka[0][2] <= m0) + (ka[0][3] <= m0);
            int c1 = (ka[1][0] <= m1) + (ka[1][1] <= m1) + (ka[1][2] <= m1) + (ka[1][3] <= m1);
            c0 = __reduce_add_sync(0xffffffffu, c0);
            c1 = __reduce_add_sync(0xffffffffu, c1);
            if (c0 >= KNN) hi0 = m0; else lo0 = m0 + 1;
            if (c1 >= KNN) hi1 = m1; else lo1 = m1 + 1;
        }
        const unsigned KV[2] = {lo0, lo1};

#pragma unroll 1
        for (int rr = 0; rr < 2; rr++) {
            const int i = iA + rr;
            const unsigned kv = KV[rr];

            int cl = 0;
#pragma unroll
            for (int c = 0; c < 4; c++) cl += (ka[rr][c] < kv) ? 1 : 0;
            int c0tot = __reduce_add_sync(0xffffffffu, cl);
            int rem = KNN - c0tot;          // ties to take, in ascending j

            bool sel[4];
#pragma unroll
            for (int c = 0; c < 4; c++) {
                bool eq = (ka[rr][c] == kv);
                unsigned bal = __ballot_sync(0xffffffffu, eq);
                int before = __popc(bal & lmask);
                sel[c] = (ka[rr][c] < kv) || (eq && before < rem);
                rem -= __popc(bal);
            }
            int base = 0;
#pragma unroll
            for (int c = 0; c < 4; c++) {
                unsigned bs = __ballot_sync(0xffffffffu, sel[c]);
                if (sel[c]) sList[i * KNN + base + __popc(bs & lmask)] = l + 32 * c;
                base += __popc(bs);
            }
            __syncwarp();

            // aggregate: componentwise max of selected q rows, then elu(p+max)
            const int fo = 4 * l;
            float4 qm = make_float4(-3.0e38f, -3.0e38f, -3.0e38f, -3.0e38f);
#pragma unroll 4
            for (int it = 0; it < KNN; it++) {
                int j = sList[i * KNN + it];
                float4 qv = *(const float4*)(sQ + j * 128 + fo);
                qm.x = fmaxf(qm.x, qv.x);
                qm.y = fmaxf(qm.y, qv.y);
                qm.z = fmaxf(qm.z, qv.z);
                qm.w = fmaxf(qm.w, qv.w);
            }
            float4 pv = *(const float4*)(PQg + (size_t)i * 256 + fo);
            float4 ov;
            ov.x = elu_fast(pv.x + qm.x);
            ov.y = elu_fast(pv.y + qm.y);
            ov.z = elu_fast(pv.z + qm.z);
            ov.w = elu_fast(pv.w + qm.w);
            *(float4*)(OUT + ((size_t)g * NPG + i) * HID + fo) = ov;
        }
    }
}

// ---------------- sum-pool + output MLP -------------------------------------
__global__ __launch_bounds__(128) void pool_mlp(
    const float* __restrict__ X,
    const float* __restrict__ w1, const float* __restrict__ b1,
    const float* __restrict__ w2, const float* __restrict__ b2,
    const float* __restrict__ w3, const float* __restrict__ b3,
    const float* __restrict__ w4, const float* __restrict__ b4,
    float* __restrict__ out)
{
    __shared__ float pooled[128];
    __shared__ float o1[64];
    __shared__ float o2[32];
    __shared__ float o3[32];
    const int g = blockIdx.x, t = threadIdx.x;
    const float* Xg = X + (size_t)g * NPG * HID;

    float s = 0.0f;
    for (int n = 0; n < NPG; n++) s += Xg[n * HID + t];
    pooled[t] = s;
    __syncthreads();

    if (t < 64) {
        float a = b1[t];
        for (int d = 0; d < 128; d++) a += pooled[d] * w1[d * 64 + t];
        o1[t] = elu_fast(a);
    }
    __syncthreads();
    if (t < 32) {
        float a = b2[t];
        for (int d = 0; d < 64; d++) a += o1[d] * w2[d * 32 + t];
        o2[t] = elu_fast(a);
    }
    __syncthreads();
    if (t < 32) {
        float a = b3[t];
        for (int d = 0; d < 32; d++) a += o2[d] * w3[d * 32 + t];
        o3[t] = elu_fast(a);
    }
    __syncthreads();
    if (t < 6) {
        float a = b4[t];
        for (int d = 0; d < 32; d++) a += o3[d] * w4[d * 6 + t];
        out[g * 6 + t] = a;
    }
}

__global__ void copy_batch(const int* __restrict__ b, float* __restrict__ out)
{
    int i = blockIdx.x * 256 + threadIdx.x;
    if (i < NODES) out[i] = (float)b[i];
}

// ---------------------------------------------------------------------------
extern "C" void kernel_launch(void* const* d_in, const int* in_sizes, int n_in,
                              void* d_out, int out_size)
{
    const float* x_pf    = (const float*)d_in[0];
    const float* enc_w1  = (const float*)d_in[1];
    const float* enc_b1  = (const float*)d_in[2];
    const float* enc_w2  = (const float*)d_in[3];
    const float* enc_b2  = (const float*)d_in[4];
    const float* conv_w[3] = {(const float*)d_in[5], (const float*)d_in[7], (const float*)d_in[9]};
    const float* conv_b[3] = {(const float*)d_in[6], (const float*)d_in[8], (const float*)d_in[10]};
    const float* out_w1  = (const float*)d_in[11];
    const float* out_b1  = (const float*)d_in[12];
    const float* out_w2  = (const float*)d_in[13];
    const float* out_b2  = (const float*)d_in[14];
    const float* out_w3  = (const float*)d_in[15];
    const float* out_b3  = (const float*)d_in[16];
    const float* out_w4  = (const float*)d_in[17];
    const float* out_b4  = (const float*)d_in[18];
    const int*   batch   = (const int*)d_in[19];

    float *featA, *featB, *pq, *wc;
    cudaGetSymbolAddress((void**)&featA, g_feat_a);
    cudaGetSymbolAddress((void**)&featB, g_feat_b);
    cudaGetSymbolAddress((void**)&pq,    g_pq);
    cudaGetSymbolAddress((void**)&wc,    g_wc);

    cudaFuncSetAttribute(knn_agg, cudaFuncAttributeMaxDynamicSharedMemorySize, SMEM_KNN);

    // encoder
    mm_kernel<<<dim3(NODES / 128, 1), 256>>>(x_pf,  enc_w1, enc_b1, 128, 1, featB, NODES, 128, 16);
    mm_kernel<<<dim3(NODES / 128, 1), 256>>>(featB, enc_w2, enc_b2, 128, 1, featA, NODES, 128, 128);

    // 3 dynamic edge convs
    float* cur = featA;
    float* nxt = featB;
    for (int cidx = 0; cidx < 3; cidx++) {
        build_wcat<<<128, 256>>>(conv_w[cidx], wc);
        mm_kernel<<<dim3(NODES / 128, 2), 256>>>(cur, wc, conv_b[cidx], 128, 0, pq, NODES, 256, 128);
        knn_agg<<<NG, 512, SMEM_KNN>>>(cur, pq, nxt);
        float* t = cur; cur = nxt; nxt = t;
    }

    pool_mlp<<<NG, 128>>>(cur, out_w1, out_b1, out_w2, out_b2,
                          out_w3, out_b3, out_w4, out_b4, (float*)d_out);

    copy_batch<<<(NODES + 255) / 256, 256>>>(batch, (float*)d_out + NG * 6);
}

// round 3
// speedup vs baseline: 2.0657x; 1.3018x over previous
#include <cuda_runtime.h>
#include <cstdint>

#define NODES   16384
#define NPG     128
#define NG      128
#define HID     128
#define KNN     24

typedef unsigned long long u64;

// ---------------- scratch ----------------
__device__ float g_feat_a[NODES * HID];
__device__ float g_feat_b[NODES * HID];
__device__ float g_pq[NODES * 2 * HID];
__device__ float g_wc[HID * 2 * HID];

__device__ __forceinline__ float elu_fast(float v) {
    return v > 0.0f ? v : (__expf(v) - 1.0f);
}

__device__ __forceinline__ unsigned fkey(float v) {
    unsigned b = __float_as_uint(v);
    return b ^ ((b & 0x80000000u) ? 0xffffffffu : 0x80000000u);
}

// ---- packed fp32x2 helpers (sm_103a FFMA2) ----
__device__ __forceinline__ u64 pack2(float lo, float hi) {
    u64 r; asm("mov.b64 %0,{%1,%2};" : "=l"(r) : "f"(lo), "f"(hi)); return r;
}
__device__ __forceinline__ void unpack2(u64 v, float& lo, float& hi) {
    asm("mov.b64 {%0,%1},%2;" : "=f"(lo), "=f"(hi) : "l"(v));
}
__device__ __forceinline__ void dfma(u64& d, u64 a, u64 b) {
    asm("fma.rn.f32x2 %0,%1,%2,%0;" : "+l"(d) : "l"(a), "l"(b));
}

// ---------------- 128x128-tile fp32 matmul (FFMA2): C = act(A*B + bias) ----
// A: MxK row-major, B: KxN row-major, C: MxN. M%128==0, N%128==0, K%16==0.
__global__ __launch_bounds__(256, 2) void mm_kernel(
    const float* __restrict__ A, const float* __restrict__ B,
    const float* __restrict__ bias, int biasLimit, int doElu,
    float* __restrict__ C, int M, int N, int K)
{
    __shared__ float As[16 * 132];   // [k][m], stride 132 (16B-aligned rows)
    __shared__ float Bs[16 * 128];   // [k][n]

    const int tid = threadIdx.x;
    const int tx = tid & 15;         // 8 cols each
    const int ty = tid >> 4;         // 8 rows each (4 row-pairs)
    const int rowBase = blockIdx.x * 128;
    const int colBase = blockIdx.y * 128;

    u64 acc2[4][8];                  // [row-pair][col], f32x2 over rows
#pragma unroll
    for (int r = 0; r < 4; r++)
#pragma unroll
        for (int c = 0; c < 8; c++) acc2[r][c] = 0ull;

    for (int kk = 0; kk < K; kk += 16) {
#pragma unroll
        for (int t = 0; t < 8; t++) {
            int idx = t * 256 + tid;
            int m = idx >> 4, k = idx & 15;
            As[k * 132 + m] = A[(size_t)(rowBase + m) * K + kk + k];
        }
#pragma unroll
        for (int t = 0; t < 8; t++) {
            int idx = t * 256 + tid;
            int k = idx >> 7, n = idx & 127;
            Bs[k * 128 + n] = B[(size_t)(kk + k) * N + colBase + n];
        }
        __syncthreads();
#pragma unroll
        for (int k = 0; k < 16; k++) {
            const float* ap = &As[k * 132 + ty * 8];
            ulonglong2 t0 = *(const ulonglong2*)(ap);
            ulonglong2 t1 = *(const ulonglong2*)(ap + 4);
            u64 a[4] = {t0.x, t0.y, t1.x, t1.y};
            float4 b0 = *(const float4*)&Bs[k * 128 + tx * 8];
            float4 b1 = *(const float4*)&Bs[k * 128 + tx * 8 + 4];
            u64 bd[8];
            bd[0] = pack2(b0.x, b0.x); bd[1] = pack2(b0.y, b0.y);
            bd[2] = pack2(b0.z, b0.z); bd[3] = pack2(b0.w, b0.w);
            bd[4] = pack2(b1.x, b1.x); bd[5] = pack2(b1.y, b1.y);
            bd[6] = pack2(b1.z, b1.z); bd[7] = pack2(b1.w, b1.w);
#pragma unroll
            for (int r = 0; r < 4; r++)
#pragma unroll
                for (int c = 0; c < 8; c++) dfma(acc2[r][c], a[r], bd[c]);
        }
        __syncthreads();
    }

#pragma unroll
    for (int r = 0; r < 4; r++) {
        int row0 = rowBase + ty * 8 + 2 * r;
        float lo[8], hi[8];
#pragma unroll
        for (int c = 0; c < 8; c++) unpack2(acc2[r][c], lo[c], hi[c]);
#pragma unroll
        for (int c = 0; c < 8; c++) {
            int col = colBase + tx * 8 + c;
            if (col < biasLimit) { float bb = bias[col]; lo[c] += bb; hi[c] += bb; }
            if (doElu) { lo[c] = elu_fast(lo[c]); hi[c] = elu_fast(hi[c]); }
        }
        float* p0 = C + (size_t)row0 * N + colBase + tx * 8;
        float* p1 = p0 + N;
        *(float4*)p0       = make_float4(lo[0], lo[1], lo[2], lo[3]);
        *(float4*)(p0 + 4) = make_float4(lo[4], lo[5], lo[6], lo[7]);
        *(float4*)p1       = make_float4(hi[0], hi[1], hi[2], hi[3]);
        *(float4*)(p1 + 4) = make_float4(hi[4], hi[5], hi[6], hi[7]);
    }
}

// ---------------- build [Wa-Wb | Wb] (128 x 256) from conv_w (256 x 128) ---
__global__ void build_wcat(const float* __restrict__ w, float* __restrict__ wc)
{
    int idx = blockIdx.x * 256 + threadIdx.x;
    int d = idx >> 8;
    int n = idx & 255;
    float v;
    if (n < 128) v = w[d * 128 + n] - w[(128 + d) * 128 + n];
    else         v = w[(128 + d) * 128 + (n - 128)];
    wc[idx] = v;
}

// ---------------- fused per-graph kNN + radix top-k + aggregate ------------
#define SXT_S 132
#define SD_S  132
#define SMEM_KNN ((128*SXT_S + 128*SD_S + 128*128 + 128 + 128*KNN) * 4)

__global__ __launch_bounds__(512, 1) void knn_agg(
    const float* __restrict__ X, const float* __restrict__ PQ,
    float* __restrict__ OUT)
{
    extern __shared__ float sm[];
    float* sXT = sm;                         // [f][n] stride 132
    float* sD  = sXT + 128 * SXT_S;          // [i][j] stride 132
    float* sQ  = sD  + 128 * SD_S;           // [n][f] stride 128
    float* sSq = sQ  + 128 * 128;            // [n]
    int*   sList = (int*)(sSq + 128);        // [i][24]

    const int g   = blockIdx.x;
    const int tid = threadIdx.x;
    const float* Xg  = X  + (size_t)g * NPG * HID;
    const float* PQg = PQ + (size_t)g * NPG * 2 * HID;

    // phase 1: load X (transposed) and q tile
    for (int idx = tid; idx < NPG * HID; idx += 512) {
        int n = idx >> 7, f = idx & 127;
        sXT[f * SXT_S + n] = Xg[idx];
        sQ[n * 128 + f]    = PQg[n * 256 + 128 + f];
    }
    __syncthreads();

    // phase 2+3a concurrent: warps 0-7 accumulate Gram (FFMA2),
    //                        warps 8-11 compute squared norms.
    u64 acc2[4][8];
    int i0 = 0, j0 = 0;
    if (tid < 256) {
        const int tx = tid & 15, ty = tid >> 4;
        i0 = ty * 8; j0 = tx * 8;
#pragma unroll
        for (int r = 0; r < 4; r++)
#pragma unroll
            for (int c = 0; c < 8; c++) acc2[r][c] = 0ull;

#pragma unroll 2
        for (int d = 0; d < 128; d++) {
            const float* rowp = sXT + d * SXT_S;
            ulonglong2 t0 = *(const ulonglong2*)(rowp + i0);
            ulonglong2 t1 = *(const ulonglong2*)(rowp + i0 + 4);
            u64 a[4] = {t0.x, t0.y, t1.x, t1.y};
            float4 b0 = *(const float4*)(rowp + j0);
            float4 b1 = *(const float4*)(rowp + j0 + 4);
            u64 bd[8];
            bd[0] = pack2(b0.x, b0.x); bd[1] = pack2(b0.y, b0.y);
            bd[2] = pack2(b0.z, b0.z); bd[3] = pack2(b0.w, b0.w);
            bd[4] = pack2(b1.x, b1.x); bd[5] = pack2(b1.y, b1.y);
            bd[6] = pack2(b1.z, b1.z); bd[7] = pack2(b1.w, b1.w);
#pragma unroll
            for (int r = 0; r < 4; r++)
#pragma unroll
                for (int c = 0; c < 8; c++) dfma(acc2[r][c], a[r], bd[c]);
        }
    } else if (tid - 256 < 128) {
        const int n = tid - 256;
        float s = 0.0f;
#pragma unroll 4
        for (int d = 0; d < 128; d++) {
            float v = sXT[d * SXT_S + n];
            s += v * v;
        }
        sSq[n] = s;
    }
    __syncthreads();

    // phase 3b: epilogue -> d2
    if (tid < 256) {
        float sqj[8];
#pragma unroll
        for (int c = 0; c < 8; c++) sqj[c] = sSq[j0 + c];
#pragma unroll
        for (int r = 0; r < 4; r++) {
            int ia = i0 + 2 * r;
            float sqa = sSq[ia], sqb = sSq[ia + 1];
            float lo[8], hi[8];
#pragma unroll
            for (int c = 0; c < 8; c++) unpack2(acc2[r][c], lo[c], hi[c]);
            float4 v0, v1, w0, w1;
            v0.x = sqa + sqj[0] - 2.0f*lo[0]; v0.y = sqa + sqj[1] - 2.0f*lo[1];
            v0.z = sqa + sqj[2] - 2.0f*lo[2]; v0.w = sqa + sqj[3] - 2.0f*lo[3];
            v1.x = sqa + sqj[4] - 2.0f*lo[4]; v1.y = sqa + sqj[5] - 2.0f*lo[5];
            v1.z = sqa + sqj[6] - 2.0f*lo[6]; v1.w = sqa + sqj[7] - 2.0f*lo[7];
            w0.x = sqb + sqj[0] - 2.0f*hi[0]; w0.y = sqb + sqj[1] - 2.0f*hi[1];
            w0.z = sqb + sqj[2] - 2.0f*hi[2]; w0.w = sqb + sqj[3] - 2.0f*hi[3];
            w1.x = sqb + sqj[4] - 2.0f*hi[4]; w1.y = sqb + sqj[5] - 2.0f*hi[5];
            w1.z = sqb + sqj[6] - 2.0f*hi[6]; w1.w = sqb + sqj[7] - 2.0f*hi[7];
            *(float4*)&sD[ia * SD_S + j0]           = v0;
            *(float4*)&sD[ia * SD_S + j0 + 4]       = v1;
            *(float4*)&sD[(ia + 1) * SD_S + j0]     = w0;
            *(float4*)&sD[(ia + 1) * SD_S + j0 + 4] = w1;
        }
    }
    __syncthreads();

    // phase 4: per-row radix-select threshold + neighbor list + aggregate
    const int w = tid >> 5;
    const int l = tid & 31;
    const unsigned lmask = (1u << l) - 1u;
    const int rowBase = w * 8;

    for (int pp = 0; pp < 4; pp++) {
        const int iA = rowBase + 2 * pp;

        unsigned ka[2][4];
#pragma unroll
        for (int rr = 0; rr < 2; rr++)
#pragma unroll
            for (int c = 0; c < 4; c++)
                ka[rr][c] = fkey(sD[(iA + rr) * SD_S + l + 32 * c]);

        unsigned lo0 = 0, hi0 = 0xffffffffu, lo1 = 0, hi1 = 0xffffffffu;
#pragma unroll 1
        for (int it = 0; it < 32; it++) {
            unsigned m0 = lo0 + ((hi0 - lo0) >> 1);
            unsigned m1 = lo1 + ((hi1 - lo1) >> 1);
            int c0 = (ka[0][0] <= m0) + (ka[0][1] <= m0) + (ka[0][2] <= m0) + (ka[0][3] <= m0);
            int c1 = (ka[1][0] <= m1) + (ka[1][1] <= m1) + (ka[1][2] <= m1) + (ka[1][3] <= m1);
            c0 = __reduce_add_sync(0xffffffffu, c0);
            c1 = __reduce_add_sync(0xffffffffu, c1);
            if (c0 >= KNN) hi0 = m0; else lo0 = m0 + 1;
            if (c1 >= KNN) hi1 = m1; else lo1 = m1 + 1;
        }
        const unsigned KV[2] = {lo0, lo1};

#pragma unroll 1
        for (int rr = 0; rr < 2; rr++) {
            const int i = iA + rr;
            const unsigned kv = KV[rr];

            int cl = 0;
#pragma unroll
            for (int c = 0; c < 4; c++) cl += (ka[rr][c] < kv) ? 1 : 0;
            int c0tot = __reduce_add_sync(0xffffffffu, cl);
            int rem = KNN - c0tot;

            bool sel[4];
#pragma unroll
            for (int c = 0; c < 4; c++) {
                bool eq = (ka[rr][c] == kv);
                unsigned bal = __ballot_sync(0xffffffffu, eq);
                int before = __popc(bal & lmask);
                sel[c] = (ka[rr][c] < kv) || (eq && before < rem);
                rem -= __popc(bal);
            }
            int base = 0;
#pragma unroll
            for (int c = 0; c < 4; c++) {
                unsigned bs = __ballot_sync(0xffffffffu, sel[c]);
                if (sel[c]) sList[i * KNN + base + __popc(bs & lmask)] = l + 32 * c;
                base += __popc(bs);
            }
            __syncwarp();

            const int fo = 4 * l;
            float4 qm = make_float4(-3.0e38f, -3.0e38f, -3.0e38f, -3.0e38f);
#pragma unroll 4
            for (int it = 0; it < KNN; it++) {
                int j = sList[i * KNN + it];
                float4 qv = *(const float4*)(sQ + j * 128 + fo);
                qm.x = fmaxf(qm.x, qv.x);
                qm.y = fmaxf(qm.y, qv.y);
                qm.z = fmaxf(qm.z, qv.z);
                qm.w = fmaxf(qm.w, qv.w);
            }
            float4 pv = *(const float4*)(PQg + (size_t)i * 256 + fo);
            float4 ov;
            ov.x = elu_fast(pv.x + qm.x);
            ov.y = elu_fast(pv.y + qm.y);
            ov.z = elu_fast(pv.z + qm.z);
            ov.w = elu_fast(pv.w + qm.w);
            *(float4*)(OUT + ((size_t)g * NPG + i) * HID + fo) = ov;
        }
    }
}

// ---------------- sum-pool + output MLP -------------------------------------
__global__ __launch_bounds__(128) void pool_mlp(
    const float* __restrict__ X,
    const float* __restrict__ w1, const float* __restrict__ b1,
    const float* __restrict__ w2, const float* __restrict__ b2,
    const float* __restrict__ w3, const float* __restrict__ b3,
    const float* __restrict__ w4, const float* __restrict__ b4,
    float* __restrict__ out)
{
    __shared__ float pooled[128];
    __shared__ float o1[64];
    __shared__ float o2[32];
    __shared__ float o3[32];
    const int g = blockIdx.x, t = threadIdx.x;
    const float* Xg = X + (size_t)g * NPG * HID;

    float s = 0.0f;
    for (int n = 0; n < NPG; n++) s += Xg[n * HID + t];
    pooled[t] = s;
    __syncthreads();

    if (t < 64) {
        float a = b1[t];
        for (int d = 0; d < 128; d++) a += pooled[d] * w1[d * 64 + t];
        o1[t] = elu_fast(a);
    }
    __syncthreads();
    if (t < 32) {
        float a = b2[t];
        for (int d = 0; d < 64; d++) a += o1[d] * w2[d * 32 + t];
        o2[t] = elu_fast(a);
    }
    __syncthreads();
    if (t < 32) {
        float a = b3[t];
        for (int d = 0; d < 32; d++) a += o2[d] * w3[d * 32 + t];
        o3[t] = elu_fast(a);
    }
    __syncthreads();
    if (t < 6) {
        float a = b4[t];
        for (int d = 0; d < 32; d++) a += o3[d] * w4[d * 6 + t];
        out[g * 6 + t] = a;
    }
}

__global__ void copy_batch(const int* __restrict__ b, float* __restrict__ out)
{
    int i = blockIdx.x * 256 + threadIdx.x;
    if (i < NODES) out[i] = (float)b[i];
}

// ---------------------------------------------------------------------------
extern "C" void kernel_launch(void* const* d_in, const int* in_sizes, int n_in,
                              void* d_out, int out_size)
{
    const float* x_pf    = (const float*)d_in[0];
    const float* enc_w1  = (const float*)d_in[1];
    const float* enc_b1  = (const float*)d_in[2];
    const float* enc_w2  = (const float*)d_in[3];
    const float* enc_b2  = (const float*)d_in[4];
    const float* conv_w[3] = {(const float*)d_in[5], (const float*)d_in[7], (const float*)d_in[9]};
    const float* conv_b[3] = {(const float*)d_in[6], (const float*)d_in[8], (const float*)d_in[10]};
    const float* out_w1  = (const float*)d_in[11];
    const float* out_b1  = (const float*)d_in[12];
    const float* out_w2  = (const float*)d_in[13];
    const float* out_b2  = (const float*)d_in[14];
    const float* out_w3  = (const float*)d_in[15];
    const float* out_b3  = (const float*)d_in[16];
    const float* out_w4  = (const float*)d_in[17];
    const float* out_b4  = (const float*)d_in[18];
    const int*   batch   = (const int*)d_in[19];

    float *featA, *featB, *pq, *wc;
    cudaGetSymbolAddress((void**)&featA, g_feat_a);
    cudaGetSymbolAddress((void**)&featB, g_feat_b);
    cudaGetSymbolAddress((void**)&pq,    g_pq);
    cudaGetSymbolAddress((void**)&wc,    g_wc);

    cudaFuncSetAttribute(knn_agg, cudaFuncAttributeMaxDynamicSharedMemorySize, SMEM_KNN);

    // encoder
    mm_kernel<<<dim3(NODES / 128, 1), 256>>>(x_pf,  enc_w1, enc_b1, 128, 1, featB, NODES, 128, 16);
    mm_kernel<<<dim3(NODES / 128, 1), 256>>>(featB, enc_w2, enc_b2, 128, 1, featA, NODES, 128, 128);

    // 3 dynamic edge convs
    float* cur = featA;
    float* nxt = featB;
    for (int cidx = 0; cidx < 3; cidx++) {
        build_wcat<<<128, 256>>>(conv_w[cidx], wc);
        mm_kernel<<<dim3(NODES / 128, 2), 256>>>(cur, wc, conv_b[cidx], 128, 0, pq, NODES, 256, 128);
        knn_agg<<<NG, 512, SMEM_KNN>>>(cur, pq, nxt);
        float* t = cur; cur = nxt; nxt = t;
    }

    pool_mlp<<<NG, 128>>>(cur, out_w1, out_b1, out_w2, out_b2,
                          out_w3, out_b3, out_w4, out_b4, (float*)d_out);

    copy_batch<<<(NODES + 255) / 256, 256>>>(batch, (float*)d_out + NG * 6);
}

// round 5
// speedup vs baseline: 2.2146x; 1.0721x over previous
#include <cuda_runtime.h>
#include <cstdint>

#define NODES   16384
#define NPG     128
#define NG      128
#define HID     128
#define KNN     24

typedef unsigned long long u64;

// ---------------- scratch ----------------
__device__ float g_feat_a[NODES * HID];
__device__ float g_feat_b[NODES * HID];
__device__ float g_pq[NODES * 2 * HID];
__device__ float g_wc[HID * 2 * HID];

__device__ __forceinline__ float elu_fast(float v) {
    return v > 0.0f ? v : (__expf(v) - 1.0f);
}

__device__ __forceinline__ unsigned fkey(float v) {
    unsigned b = __float_as_uint(v);
    return b ^ ((b & 0x80000000u) ? 0xffffffffu : 0x80000000u);
}

// ---- packed fp32x2 helpers (sm_103a FFMA2) ----
__device__ __forceinline__ u64 pack2(float lo, float hi) {
    u64 r; asm("mov.b64 %0,{%1,%2};" : "=l"(r) : "f"(lo), "f"(hi)); return r;
}
__device__ __forceinline__ void unpack2(u64 v, float& lo, float& hi) {
    asm("mov.b64 {%0,%1},%2;" : "=f"(lo), "=f"(hi) : "l"(v));
}
__device__ __forceinline__ void dfma(u64& d, u64 a, u64 b) {
    asm("fma.rn.f32x2 %0,%1,%2,%0;" : "+l"(d) : "l"(a), "l"(b));
}

// ---- cp.async helpers ----
__device__ __forceinline__ void cp16(void* smem, const void* gmem) {
    unsigned s = (unsigned)__cvta_generic_to_shared(smem);
    asm volatile("cp.async.cg.shared.global [%0], [%1], 16;\n" :: "r"(s), "l"(gmem));
}
__device__ __forceinline__ void cp_commit() { asm volatile("cp.async.commit_group;\n"); }
__device__ __forceinline__ void cp_wait0()  { asm volatile("cp.async.wait_group 0;\n"); }

// ---------------- pipelined 128x128-tile fp32 matmul (FFMA2) ---------------
// A: MxK row-major, B: KxN row-major, C: MxN. M%128==0, N%128==0, K%16==0.
__global__ __launch_bounds__(256, 2) void mm_kernel(
    const float* __restrict__ A, const float* __restrict__ B,
    const float* __restrict__ bias, int biasLimit, int doElu,
    float* __restrict__ C, int M, int N, int K)
{
    __shared__ float As[2][16 * 132];   // [k][m], stride 132
    __shared__ float Bs[2][16 * 128];   // [k][n]

    const int tid = threadIdx.x;
    const int tx = tid & 15;
    const int ty = tid >> 4;
    const int rowBase = blockIdx.x * 128;
    const int colBase = blockIdx.y * 128;

    u64 acc2[4][8];
#pragma unroll
    for (int r = 0; r < 4; r++)
#pragma unroll
        for (int c = 0; c < 8; c++) acc2[r][c] = 0ull;

    // staging index precompute
    int am[8], ak[8];
#pragma unroll
    for (int t = 0; t < 8; t++) {
        int idx = t * 256 + tid;
        am[t] = idx >> 4; ak[t] = idx & 15;
    }
    // Bs tile: 16 rows x 128 floats = 2048 floats = 512 x 16B chunks; 2/thread
    int bk[2], bn[2];
#pragma unroll
    for (int t = 0; t < 2; t++) {
        int idx = t * 256 + tid;            // 0..511
        bk[t] = idx >> 5;                   // 0..15
        bn[t] = (idx & 31) * 4;             // 0..124
    }

    float aReg[8];
    // prologue: tile kk=0
#pragma unroll
    for (int t = 0; t < 8; t++)
        aReg[t] = A[(size_t)(rowBase + am[t]) * K + ak[t]];
#pragma unroll
    for (int t = 0; t < 2; t++)
        cp16(&Bs[0][bk[t] * 128 + bn[t]], &B[(size_t)bk[t] * N + colBase + bn[t]]);
    cp_commit();
#pragma unroll
    for (int t = 0; t < 8; t++)
        As[0][ak[t] * 132 + am[t]] = aReg[t];
    cp_wait0();
    __syncthreads();

    int buf = 0;
    for (int kk = 0; kk < K; kk += 16) {
        const int nkk = kk + 16;
        if (nkk < K) {
#pragma unroll
            for (int t = 0; t < 8; t++)
                aReg[t] = A[(size_t)(rowBase + am[t]) * K + nkk + ak[t]];
#pragma unroll
            for (int t = 0; t < 2; t++)
                cp16(&Bs[buf ^ 1][bk[t] * 128 + bn[t]],
                     &B[(size_t)(nkk + bk[t]) * N + colBase + bn[t]]);
            cp_commit();
        }

        const float* __restrict__ Asb = As[buf];
        const float* __restrict__ Bsb = Bs[buf];
#pragma unroll
        for (int k = 0; k < 16; k++) {
            const float* ap = &Asb[k * 132 + ty * 8];
            ulonglong2 t0 = *(const ulonglong2*)(ap);
            ulonglong2 t1 = *(const ulonglong2*)(ap + 4);
            u64 a[4] = {t0.x, t0.y, t1.x, t1.y};
            float4 b0 = *(const float4*)&Bsb[k * 128 + tx * 8];
            float4 b1 = *(const float4*)&Bsb[k * 128 + tx * 8 + 4];
            u64 bd[8];
            bd[0] = pack2(b0.x, b0.x); bd[1] = pack2(b0.y, b0.y);
            bd[2] = pack2(b0.z, b0.z); bd[3] = pack2(b0.w, b0.w);
            bd[4] = pack2(b1.x, b1.x); bd[5] = pack2(b1.y, b1.y);
            bd[6] = pack2(b1.z, b1.z); bd[7] = pack2(b1.w, b1.w);
#pragma unroll
            for (int r = 0; r < 4; r++)
#pragma unroll
                for (int c = 0; c < 8; c++) dfma(acc2[r][c], a[r], bd[c]);
        }

        if (nkk < K) {
#pragma unroll
            for (int t = 0; t < 8; t++)
                As[buf ^ 1][ak[t] * 132 + am[t]] = aReg[t];
            cp_wait0();
            __syncthreads();
            buf ^= 1;
        }
    }

#pragma unroll
    for (int r = 0; r < 4; r++) {
        int row0 = rowBase + ty * 8 + 2 * r;
        float lo[8], hi[8];
#pragma unroll
        for (int c = 0; c < 8; c++) unpack2(acc2[r][c], lo[c], hi[c]);
#pragma unroll
        for (int c = 0; c < 8; c++) {
            int col = colBase + tx * 8 + c;
            if (col < biasLimit) { float bb = bias[col]; lo[c] += bb; hi[c] += bb; }
            if (doElu) { lo[c] = elu_fast(lo[c]); hi[c] = elu_fast(hi[c]); }
        }
        float* p0 = C + (size_t)row0 * N + colBase + tx * 8;
        float* p1 = p0 + N;
        *(float4*)p0       = make_float4(lo[0], lo[1], lo[2], lo[3]);
        *(float4*)(p0 + 4) = make_float4(lo[4], lo[5], lo[6], lo[7]);
        *(float4*)p1       = make_float4(hi[0], hi[1], hi[2], hi[3]);
        *(float4*)(p1 + 4) = make_float4(hi[4], hi[5], hi[6], hi[7]);
    }
}

// ---------------- build [Wa-Wb | Wb] (128 x 256) from conv_w (256 x 128) ---
__global__ void build_wcat(const float* __restrict__ w, float* __restrict__ wc)
{
    int idx = blockIdx.x * 256 + threadIdx.x;
    int d = idx >> 8;
    int n = idx & 255;
    float v;
    if (n < 128) v = w[d * 128 + n] - w[(128 + d) * 128 + n];
    else         v = w[(128 + d) * 128 + (n - 128)];
    wc[idx] = v;
}

// ---------------- fused per-graph kNN + radix top-k + aggregate ------------
#define SXT_S 132
#define SD_S  132
#define SMEM_KNN ((128*SXT_S + 128*SD_S + 128*128 + 128 + 128*KNN) * 4)

__global__ __launch_bounds__(512, 1) void knn_agg(
    const float* __restrict__ X, const float* __restrict__ PQ,
    float* __restrict__ OUT)
{
    extern __shared__ float sm[];
    float* sXT = sm;                         // [f][n] stride 132
    float* sD  = sXT + 128 * SXT_S;          // [i][j] stride 132
    float* sQ  = sD  + 128 * SD_S;           // [n][f] stride 128
    float* sSq = sQ  + 128 * 128;            // [n]
    int*   sList = (int*)(sSq + 128);        // [i][24]

    const int g   = blockIdx.x;
    const int tid = threadIdx.x;
    const float* Xg  = X  + (size_t)g * NPG * HID;
    const float* PQg = PQ + (size_t)g * NPG * 2 * HID;

    // async copy of q tile (consumed only in phase 4): 4096 16B chunks, 8/thread
#pragma unroll
    for (int t = 0; t < 8; t++) {
        int idx = t * 512 + tid;
        int n = idx >> 5, c4 = (idx & 31) * 4;
        cp16(&sQ[n * 128 + c4], &PQg[n * 256 + 128 + c4]);
    }
    cp_commit();

    // phase 1: load X (transposed)
    for (int idx = tid; idx < NPG * HID; idx += 512) {
        int n = idx >> 7, f = idx & 127;
        sXT[f * SXT_S + n] = Xg[idx];
    }
    __syncthreads();

    // phase 2+3a concurrent: warps 0-7 Gram (FFMA2), warps 8-11 squared norms
    u64 acc2[4][8];
    int i0 = 0, j0 = 0;
    if (tid < 256) {
        const int tx = tid & 15, ty = tid >> 4;
        i0 = ty * 8; j0 = tx * 8;
#pragma unroll
        for (int r = 0; r < 4; r++)
#pragma unroll
            for (int c = 0; c < 8; c++) acc2[r][c] = 0ull;

#pragma unroll 2
        for (int d = 0; d < 128; d++) {
            const float* rowp = sXT + d * SXT_S;
            ulonglong2 t0 = *(const ulonglong2*)(rowp + i0);
            ulonglong2 t1 = *(const ulonglong2*)(rowp + i0 + 4);
            u64 a[4] = {t0.x, t0.y, t1.x, t1.y};
            float4 b0 = *(const float4*)(rowp + j0);
            float4 b1 = *(const float4*)(rowp + j0 + 4);
            u64 bd[8];
            bd[0] = pack2(b0.x, b0.x); bd[1] = pack2(b0.y, b0.y);
            bd[2] = pack2(b0.z, b0.z); bd[3] = pack2(b0.w, b0.w);
            bd[4] = pack2(b1.x, b1.x); bd[5] = pack2(b1.y, b1.y);
            bd[6] = pack2(b1.z, b1.z); bd[7] = pack2(b1.w, b1.w);
#pragma unroll
            for (int r = 0; r < 4; r++)
#pragma unroll
                for (int c = 0; c < 8; c++) dfma(acc2[r][c], a[r], bd[c]);
        }
    } else if (tid - 256 < 128) {
        const int n = tid - 256;
        float s = 0.0f;
#pragma unroll 4
        for (int d = 0; d < 128; d++) {
            float v = sXT[d * SXT_S + n];
            s += v * v;
        }
        sSq[n] = s;
    }
    __syncthreads();

    // phase 3b: epilogue -> d2
    if (tid < 256) {
        float sqj[8];
#pragma unroll
        for (int c = 0; c < 8; c++) sqj[c] = sSq[j0 + c];
#pragma unroll
        for (int r = 0; r < 4; r++) {
            int ia = i0 + 2 * r;
            float sqa = sSq[ia], sqb = sSq[ia + 1];
            float lo[8], hi[8];
#pragma unroll
            for (int c = 0; c < 8; c++) unpack2(acc2[r][c], lo[c], hi[c]);
            float4 v0, v1, w0, w1;
            v0.x = sqa + sqj[0] - 2.0f*lo[0]; v0.y = sqa + sqj[1] - 2.0f*lo[1];
            v0.z = sqa + sqj[2] - 2.0f*lo[2]; v0.w = sqa + sqj[3] - 2.0f*lo[3];
            v1.x = sqa + sqj[4] - 2.0f*lo[4]; v1.y = sqa + sqj[5] - 2.0f*lo[5];
            v1.z = sqa + sqj[6] - 2.0f*lo[6]; v1.w = sqa + sqj[7] - 2.0f*lo[7];
            w0.x = sqb + sqj[0] - 2.0f*hi[0]; w0.y = sqb + sqj[1] - 2.0f*hi[1];
            w0.z = sqb + sqj[2] - 2.0f*hi[2]; w0.w = sqb + sqj[3] - 2.0f*hi[3];
            w1.x = sqb + sqj[4] - 2.0f*hi[4]; w1.y = sqb + sqj[5] - 2.0f*hi[5];
            w1.z = sqb + sqj[6] - 2.0f*hi[6]; w1.w = sqb + sqj[7] - 2.0f*hi[7];
            *(float4*)&sD[ia * SD_S + j0]           = v0;
            *(float4*)&sD[ia * SD_S + j0 + 4]       = v1;
            *(float4*)&sD[(ia + 1) * SD_S + j0]     = w0;
            *(float4*)&sD[(ia + 1) * SD_S + j0 + 4] = w1;
        }
    }
    cp_wait0();          // q tile in place (issued pre-phase-1)
    __syncthreads();

    // phase 4: per-row radix-select threshold + neighbor list + aggregate
    const int w = tid >> 5;
    const int l = tid & 31;
    const unsigned lmask = (1u << l) - 1u;
    const int rowBase = w * 8;

    for (int pp = 0; pp < 4; pp++) {
        const int iA = rowBase + 2 * pp;

        unsigned ka[2][4];
#pragma unroll
        for (int rr = 0; rr < 2; rr++)
#pragma unroll
            for (int c = 0; c < 4; c++)
                ka[rr][c] = fkey(sD[(iA + rr) * SD_S + l + 32 * c]);

        unsigned lo0 = 0, hi0 = 0xffffffffu, lo1 = 0, hi1 = 0xffffffffu;
#pragma unroll 1
        for (int it = 0; it < 32; it++) {
            unsigned m0 = lo0 + ((hi0 - lo0) >> 1);
            unsigned m1 = lo1 + ((hi1 - lo1) >> 1);
            int c0 = (ka[0][0] <= m0) + (ka[0][1] <= m0) + (ka[0][2] <= m0) + (ka[0][3] <= m0);
            int c1 = (ka[1][0] <= m1) + (ka[1][1] <= m1) + (ka[1][2] <= m1) + (ka[1][3] <= m1);
            c0 = __reduce_add_sync(0xffffffffu, c0);
            c1 = __reduce_add_sync(0xffffffffu, c1);
            if (c0 >= KNN) hi0 = m0; else lo0 = m0 + 1;
            if (c1 >= KNN) hi1 = m1; else lo1 = m1 + 1;
        }
        const unsigned KV[2] = {lo0, lo1};

#pragma unroll 1
        for (int rr = 0; rr < 2; rr++) {
            const int i = iA + rr;
            const unsigned kv = KV[rr];

            const int fo = 4 * l;
            float4 pv = *(const float4*)(PQg + (size_t)i * 256 + fo);

            int cl = 0;
#pragma unroll
            for (int c = 0; c < 4; c++) cl += (ka[rr][c] < kv) ? 1 : 0;
            int c0tot = __reduce_add_sync(0xffffffffu, cl);
            int rem = KNN - c0tot;

            bool sel[4];
#pragma unroll
            for (int c = 0; c < 4; c++) {
                bool eq = (ka[rr][c] == kv);
                unsigned bal = __ballot_sync(0xffffffffu, eq);
                int before = __popc(bal & lmask);
                sel[c] = (ka[rr][c] < kv) || (eq && before < rem);
                rem -= __popc(bal);
            }
            int base = 0;
#pragma unroll
            for (int c = 0; c < 4; c++) {
                unsigned bs = __ballot_sync(0xffffffffu, sel[c]);
                if (sel[c]) sList[i * KNN + base + __popc(bs & lmask)] = l + 32 * c;
                base += __popc(bs);
            }
            __syncwarp();

            float4 qm = make_float4(-3.0e38f, -3.0e38f, -3.0e38f, -3.0e38f);
#pragma unroll 4
            for (int it = 0; it < KNN; it++) {
                int j = sList[i * KNN + it];
                float4 qv = *(const float4*)(sQ + j * 128 + fo);
                qm.x = fmaxf(qm.x, qv.x);
                qm.y = fmaxf(qm.y, qv.y);
                qm.z = fmaxf(qm.z, qv.z);
                qm.w = fmaxf(qm.w, qv.w);
            }
            float4 ov;
            ov.x = elu_fast(pv.x + qm.x);
            ov.y = elu_fast(pv.y + qm.y);
            ov.z = elu_fast(pv.z + qm.z);
            ov.w = elu_fast(pv.w + qm.w);
            *(float4*)(OUT + ((size_t)g * NPG + i) * HID + fo) = ov;
        }
    }
}

// ---------------- sum-pool + output MLP -------------------------------------
__global__ __launch_bounds__(128) void pool_mlp(
    const float* __restrict__ X,
    const float* __restrict__ w1, const float* __restrict__ b1,
    const float* __restrict__ w2, const float* __restrict__ b2,
    const float* __restrict__ w3, const float* __restrict__ b3,
    const float* __restrict__ w4, const float* __restrict__ b4,
    float* __restrict__ out)
{
    __shared__ float pooled[128];
    __shared__ float o1[64];
    __shared__ float o2[32];
    __shared__ float o3[32];
    const int g = blockIdx.x, t = threadIdx.x;
    const float* Xg = X + (size_t)g * NPG * HID;

    float s = 0.0f;
    for (int n = 0; n < NPG; n++) s += Xg[n * HID + t];
    pooled[t] = s;
    __syncthreads();

    if (t < 64) {
        float a = b1[t];
        for (int d = 0; d < 128; d++) a += pooled[d] * w1[d * 64 + t];
        o1[t] = elu_fast(a);
    }
    __syncthreads();
    if (t < 32) {
        float a = b2[t];
        for (int d = 0; d < 64; d++) a += o1[d] * w2[d * 32 + t];
        o2[t] = elu_fast(a);
    }
    __syncthreads();
    if (t < 32) {
        float a = b3[t];
        for (int d = 0; d < 32; d++) a += o2[d] * w3[d * 32 + t];
        o3[t] = elu_fast(a);
    }
    __syncthreads();
    if (t < 6) {
        float a = b4[t];
        for (int d = 0; d < 32; d++) a += o3[d] * w4[d * 6 + t];
        out[g * 6 + t] = a;
    }
}

__global__ void copy_batch(const int* __restrict__ b, float* __restrict__ out)
{
    int i = blockIdx.x * 256 + threadIdx.x;
    if (i < NODES) out[i] = (float)b[i];
}

// ---------------------------------------------------------------------------
extern "C" void kernel_launch(void* const* d_in, const int* in_sizes, int n_in,
                              void* d_out, int out_size)
{
    const float* x_pf    = (const float*)d_in[0];
    const float* enc_w1  = (const float*)d_in[1];
    const float* enc_b1  = (const float*)d_in[2];
    const float* enc_w2  = (const float*)d_in[3];
    const float* enc_b2  = (const float*)d_in[4];
    const float* conv_w[3] = {(const float*)d_in[5], (const float*)d_in[7], (const float*)d_in[9]};
    const float* conv_b[3] = {(const float*)d_in[6], (const float*)d_in[8], (const float*)d_in[10]};
    const float* out_w1  = (const float*)d_in[11];
    const float* out_b1  = (const float*)d_in[12];
    const float* out_w2  = (const float*)d_in[13];
    const float* out_b2  = (const float*)d_in[14];
    const float* out_w3  = (const float*)d_in[15];
    const float* out_b3  = (const float*)d_in[16];
    const float* out_w4  = (const float*)d_in[17];
    const float* out_b4  = (const float*)d_in[18];
    const int*   batch   = (const int*)d_in[19];

    float *featA, *featB, *pq, *wc;
    cudaGetSymbolAddress((void**)&featA, g_feat_a);
    cudaGetSymbolAddress((void**)&featB, g_feat_b);
    cudaGetSymbolAddress((void**)&pq,    g_pq);
    cudaGetSymbolAddress((void**)&wc,    g_wc);

    cudaFuncSetAttribute(knn_agg, cudaFuncAttributeMaxDynamicSharedMemorySize, SMEM_KNN);

    // encoder
    mm_kernel<<<dim3(NODES / 128, 1), 256>>>(x_pf,  enc_w1, enc_b1, 128, 1, featB, NODES, 128, 16);
    mm_kernel<<<dim3(NODES / 128, 1), 256>>>(featB, enc_w2, enc_b2, 128, 1, featA, NODES, 128, 128);

    // 3 dynamic edge convs
    float* cur = featA;
    float* nxt = featB;
    for (int cidx = 0; cidx < 3; cidx++) {
        build_wcat<<<128, 256>>>(conv_w[cidx], wc);
        mm_kernel<<<dim3(NODES / 128, 2), 256>>>(cur, wc, conv_b[cidx], 128, 0, pq, NODES, 256, 128);
        knn_agg<<<NG, 512, SMEM_KNN>>>(cur, pq, nxt);
        float* t = cur; cur = nxt; nxt = t;
    }

    pool_mlp<<<NG, 128>>>(cur, out_w1, out_b1, out_w2, out_b2,
                          out_w3, out_b3, out_w4, out_b4, (float*)d_out);

    copy_batch<<<(NODES + 255) / 256, 256>>>(batch, (float*)d_out + NG * 6);
}